// round 1
// baseline (speedup 1.0000x reference)
#include <cuda_runtime.h>
#include <cuda_bf16.h>
#include <cstdint>

// Problem constants
#define PB 8
#define PS 4096
#define PD 768
#define PN 64
#define D4 (PD / 4)          // 192 float4 per token row
#define NSEG (PB * PN)       // 512 segments
#define OUT_VEC_ELEMS ((size_t)PB * 2 * PN * PD)   // 786432

// exclusive/inclusive ends of each segment: ends[b][n] = cumsum(lens[b][0..n])
__device__ int g_ends[PB * PN];

// ---------------------------------------------------------------------------
// Kernel 1: per-batch prefix scan of sent_lengths (tiny)
// ---------------------------------------------------------------------------
__global__ void scan_kernel(const int* __restrict__ lens) {
    int b = blockIdx.x;
    if (threadIdx.x == 0) {
        int acc = 0;
        #pragma unroll 8
        for (int n = 0; n < PN; n++) {
            acc += lens[b * PN + n];
            g_ends[b * PN + n] = acc;
        }
    }
}

// ---------------------------------------------------------------------------
// Kernel 2: ragged segment mean with per-dim nonzero counts.
// One block per (b, n) segment. 192 threads, thread t owns float4 #t of D.
// ---------------------------------------------------------------------------
__global__ __launch_bounds__(192) void mean_kernel(
    const float* __restrict__ wv,
    const float* __restrict__ lmask,
    float* __restrict__ out)
{
    const int seg = blockIdx.x;
    const int b = seg >> 6;
    const int n = seg & (PN - 1);
    const int tid = threadIdx.x;

    const int start = (n == 0) ? 0 : g_ends[b * PN + n - 1];
    const int end   = g_ends[b * PN + n];

    const float4* base = reinterpret_cast<const float4*>(wv) +
                         (size_t)b * PS * D4 + tid;

    float4 acc = make_float4(0.f, 0.f, 0.f, 0.f);
    float4 cnt = make_float4(0.f, 0.f, 0.f, 0.f);

    int t = start;
    // unroll x4 for memory-level parallelism
    for (; t + 4 <= end; t += 4) {
        float4 v0 = base[(size_t)(t + 0) * D4];
        float4 v1 = base[(size_t)(t + 1) * D4];
        float4 v2 = base[(size_t)(t + 2) * D4];
        float4 v3 = base[(size_t)(t + 3) * D4];
        acc.x += v0.x + v1.x + v2.x + v3.x;
        acc.y += v0.y + v1.y + v2.y + v3.y;
        acc.z += v0.z + v1.z + v2.z + v3.z;
        acc.w += v0.w + v1.w + v2.w + v3.w;
        cnt.x += (v0.x != 0.f) + (v1.x != 0.f) + (v2.x != 0.f) + (v3.x != 0.f);
        cnt.y += (v0.y != 0.f) + (v1.y != 0.f) + (v2.y != 0.f) + (v3.y != 0.f);
        cnt.z += (v0.z != 0.f) + (v1.z != 0.f) + (v2.z != 0.f) + (v3.z != 0.f);
        cnt.w += (v0.w != 0.f) + (v1.w != 0.f) + (v2.w != 0.f) + (v3.w != 0.f);
    }
    for (; t < end; t++) {
        float4 v = base[(size_t)t * D4];
        acc.x += v.x; acc.y += v.y; acc.z += v.z; acc.w += v.w;
        cnt.x += (v.x != 0.f);
        cnt.y += (v.y != 0.f);
        cnt.z += (v.z != 0.f);
        cnt.w += (v.w != 0.f);
    }

    // block-reduce the total nonzero count across full D (for all_zero fallback)
    float tot = cnt.x + cnt.y + cnt.z + cnt.w;
    #pragma unroll
    for (int off = 16; off > 0; off >>= 1)
        tot += __shfl_down_sync(0xFFFFFFFFu, tot, off);
    __shared__ float warp_tot[6];
    const int wid = tid >> 5, lid = tid & 31;
    if (lid == 0) warp_tot[wid] = tot;
    __syncthreads();
    float total = warp_tot[0] + warp_tot[1] + warp_tot[2] +
                  warp_tot[3] + warp_tot[4] + warp_tot[5];

    float4 mean;
    mean.x = acc.x / fmaxf(cnt.x, 1.f);
    mean.y = acc.y / fmaxf(cnt.y, 1.f);
    mean.z = acc.z / fmaxf(cnt.z, 1.f);
    mean.w = acc.w / fmaxf(cnt.w, 1.f);

    if (total == 0.f) {
        // fallback to word_vectors[0,0,:]
        mean = reinterpret_cast<const float4*>(wv)[tid];
    }

    const float m = lmask[b * PN + n];
    float4 o;
    o.x = mean.x * m; o.y = mean.y * m; o.z = mean.z * m; o.w = mean.w * m;

    float4* dst = reinterpret_cast<float4*>(out) +
                  ((size_t)b * (2 * PN) + PN + n) * D4 + tid;
    *dst = o;
}

// ---------------------------------------------------------------------------
// Kernel 3: rep-token gather + masks
// ---------------------------------------------------------------------------
__global__ __launch_bounds__(192) void rep_kernel(
    const float* __restrict__ wv,
    const int* __restrict__ ids,
    const float* __restrict__ rmask,
    const float* __restrict__ lmask,
    float* __restrict__ out)
{
    const int seg = blockIdx.x;
    const int b = seg >> 6;
    const int n = seg & (PN - 1);
    const int tid = threadIdx.x;

    const int id = ids[b * PN + n];
    const float m = rmask[b * PN + n];

    const float4* src = reinterpret_cast<const float4*>(wv) +
                        ((size_t)b * PS + id) * D4 + tid;
    float4 v = *src;
    v.x *= m; v.y *= m; v.z *= m; v.w *= m;

    float4* dst = reinterpret_cast<float4*>(out) +
                  ((size_t)b * (2 * PN) + n) * D4 + tid;
    *dst = v;

    if (tid == 0) {
        float* outm = out + OUT_VEC_ELEMS;
        outm[b * (2 * PN) + n]       = m;
        outm[b * (2 * PN) + PN + n]  = lmask[b * PN + n];
    }
}

// ---------------------------------------------------------------------------
extern "C" void kernel_launch(void* const* d_in, const int* in_sizes, int n_in,
                              void* d_out, int out_size) {
    const float* wv    = (const float*)d_in[0];  // [B,S,D] f32
    const int*   ids   = (const int*)d_in[1];    // [B,N] i32
    const float* rmask = (const float*)d_in[2];  // [B,N] f32
    const int*   lens  = (const int*)d_in[3];    // [B,N] i32
    const float* lmask = (const float*)d_in[4];  // [B,N] f32
    float* out = (float*)d_out;

    scan_kernel<<<PB, 32>>>(lens);
    mean_kernel<<<NSEG, 192>>>(wv, lmask, out);
    rep_kernel<<<NSEG, 192>>>(wv, ids, rmask, lmask, out);
}

// round 2
// speedup vs baseline: 2.2018x; 2.2018x over previous
#include <cuda_runtime.h>
#include <cuda_bf16.h>
#include <cstdint>

// Problem constants
#define PB 8
#define PS 4096
#define PD 768
#define PN 64
#define D4 (PD / 4)            // 192 float4 per token row
#define NSEG (PB * PN)         // 512 segments
#define CH 64                  // tokens per chunk-block
#define NCHUNK (PS / CH)       // 64 chunks per batch
#define OUT_VEC_ELEMS ((size_t)PB * 2 * PN * PD)   // 786432

__device__ float g_sums[NSEG * PD];
__device__ float g_cnts[NSEG * PD];
__device__ int   g_ends[PB * PN];

// ---------------------------------------------------------------------------
// Kernel 1: zero the scratch accumulators + per-batch prefix scan of lengths
// ---------------------------------------------------------------------------
__global__ void zero_scan_kernel(const int* __restrict__ lens) {
    const int i = blockIdx.x * blockDim.x + threadIdx.x;
    const int stride = gridDim.x * blockDim.x;
    const float4 z = make_float4(0.f, 0.f, 0.f, 0.f);
    const int tot4 = NSEG * PD / 4;   // 98304 float4 per array
    float4* s4 = reinterpret_cast<float4*>(g_sums);
    float4* c4 = reinterpret_cast<float4*>(g_cnts);
    for (int k = i; k < tot4; k += stride) { s4[k] = z; c4[k] = z; }

    if (blockIdx.x == 0 && threadIdx.x < PB) {
        const int b = threadIdx.x;
        int acc = 0;
        #pragma unroll 8
        for (int n = 0; n < PN; n++) {
            acc += lens[b * PN + n];
            g_ends[b * PN + n] = acc;
        }
    }
}

// ---------------------------------------------------------------------------
// Kernel 2: balanced accumulate. One block per 64-token chunk; each thread
// owns one float4 of D. Per-run register accumulation, atomic flush at
// segment boundaries.
// ---------------------------------------------------------------------------
__global__ __launch_bounds__(192) void accum_kernel(const float* __restrict__ wv) {
    __shared__ int s_ends[PN];
    const int blk = blockIdx.x;
    const int b = blk >> 6;              // blk / NCHUNK
    const int c = blk & (NCHUNK - 1);
    const int tid = threadIdx.x;

    if (tid < PN) s_ends[tid] = g_ends[b * PN + tid];
    __syncthreads();

    int t = c * CH;
    const int t1 = t + CH;

    // find first segment containing token t  (seg = count of ends <= t)
    int seg = 0;
    while (s_ends[seg] <= t) seg++;

    const float4* base = reinterpret_cast<const float4*>(wv) +
                         (size_t)b * PS * D4 + tid;

    while (t < t1) {
        const int re = min(t1, s_ends[seg]);

        float4 acc = make_float4(0.f, 0.f, 0.f, 0.f);
        float4 cnt = make_float4(0.f, 0.f, 0.f, 0.f);

        int k = t;
        for (; k + 4 <= re; k += 4) {
            float4 v0 = base[(size_t)(k + 0) * D4];
            float4 v1 = base[(size_t)(k + 1) * D4];
            float4 v2 = base[(size_t)(k + 2) * D4];
            float4 v3 = base[(size_t)(k + 3) * D4];
            acc.x += v0.x + v1.x + v2.x + v3.x;
            acc.y += v0.y + v1.y + v2.y + v3.y;
            acc.z += v0.z + v1.z + v2.z + v3.z;
            acc.w += v0.w + v1.w + v2.w + v3.w;
            cnt.x += (v0.x != 0.f) + (v1.x != 0.f) + (v2.x != 0.f) + (v3.x != 0.f);
            cnt.y += (v0.y != 0.f) + (v1.y != 0.f) + (v2.y != 0.f) + (v3.y != 0.f);
            cnt.z += (v0.z != 0.f) + (v1.z != 0.f) + (v2.z != 0.f) + (v3.z != 0.f);
            cnt.w += (v0.w != 0.f) + (v1.w != 0.f) + (v2.w != 0.f) + (v3.w != 0.f);
        }
        for (; k < re; k++) {
            float4 v = base[(size_t)k * D4];
            acc.x += v.x; acc.y += v.y; acc.z += v.z; acc.w += v.w;
            cnt.x += (v.x != 0.f);
            cnt.y += (v.y != 0.f);
            cnt.z += (v.z != 0.f);
            cnt.w += (v.w != 0.f);
        }

        if (re > t) {
            float* sp = g_sums + (size_t)(b * PN + seg) * PD + tid * 4;
            float* cp = g_cnts + (size_t)(b * PN + seg) * PD + tid * 4;
            atomicAdd(sp + 0, acc.x); atomicAdd(sp + 1, acc.y);
            atomicAdd(sp + 2, acc.z); atomicAdd(sp + 3, acc.w);
            atomicAdd(cp + 0, cnt.x); atomicAdd(cp + 1, cnt.y);
            atomicAdd(cp + 2, cnt.z); atomicAdd(cp + 3, cnt.w);
        }

        t = re;
        while (t < t1 && s_ends[seg] <= t) seg++;
    }
}

// ---------------------------------------------------------------------------
// Kernel 3: finalize mean (divide, fallback, mask) + rep gather + masks
// ---------------------------------------------------------------------------
__global__ __launch_bounds__(192) void finalize_kernel(
    const float* __restrict__ wv,
    const int* __restrict__ ids,
    const float* __restrict__ rmask,
    const float* __restrict__ lmask,
    float* __restrict__ out)
{
    const int seg = blockIdx.x;
    const int b = seg >> 6;
    const int n = seg & (PN - 1);
    const int tid = threadIdx.x;

    float4 s  = reinterpret_cast<const float4*>(g_sums)[seg * D4 + tid];
    float4 cc = reinterpret_cast<const float4*>(g_cnts)[seg * D4 + tid];

    // block-reduce total nonzero count (for all_zero fallback)
    float tot = cc.x + cc.y + cc.z + cc.w;
    #pragma unroll
    for (int off = 16; off > 0; off >>= 1)
        tot += __shfl_down_sync(0xFFFFFFFFu, tot, off);
    __shared__ float warp_tot[6];
    const int wid = tid >> 5, lid = tid & 31;
    if (lid == 0) warp_tot[wid] = tot;
    __syncthreads();
    const float total = warp_tot[0] + warp_tot[1] + warp_tot[2] +
                        warp_tot[3] + warp_tot[4] + warp_tot[5];

    float4 mean;
    mean.x = s.x / fmaxf(cc.x, 1.f);
    mean.y = s.y / fmaxf(cc.y, 1.f);
    mean.z = s.z / fmaxf(cc.z, 1.f);
    mean.w = s.w / fmaxf(cc.w, 1.f);
    if (total == 0.f)
        mean = reinterpret_cast<const float4*>(wv)[tid];   // wv[0,0,:]

    const float lm = lmask[b * PN + n];
    float4 om;
    om.x = mean.x * lm; om.y = mean.y * lm;
    om.z = mean.z * lm; om.w = mean.w * lm;
    reinterpret_cast<float4*>(out)[((size_t)b * (2 * PN) + PN + n) * D4 + tid] = om;

    // rep-token gather half
    const int id = ids[b * PN + n];
    const float rm = rmask[b * PN + n];
    float4 v = reinterpret_cast<const float4*>(wv)[((size_t)b * PS + id) * D4 + tid];
    v.x *= rm; v.y *= rm; v.z *= rm; v.w *= rm;
    reinterpret_cast<float4*>(out)[((size_t)b * (2 * PN) + n) * D4 + tid] = v;

    if (tid == 0) {
        float* outm = out + OUT_VEC_ELEMS;
        outm[b * (2 * PN) + n]      = rm;
        outm[b * (2 * PN) + PN + n] = lm;
    }
}

// ---------------------------------------------------------------------------
extern "C" void kernel_launch(void* const* d_in, const int* in_sizes, int n_in,
                              void* d_out, int out_size) {
    const float* wv    = (const float*)d_in[0];  // [B,S,D] f32
    const int*   ids   = (const int*)d_in[1];    // [B,N] i32
    const float* rmask = (const float*)d_in[2];  // [B,N] f32
    const int*   lens  = (const int*)d_in[3];    // [B,N] i32
    const float* lmask = (const float*)d_in[4];  // [B,N] f32
    float* out = (float*)d_out;

    zero_scan_kernel<<<192, 256>>>(lens);
    accum_kernel<<<PB * NCHUNK, 192>>>(wv);
    finalize_kernel<<<NSEG, 192>>>(wv, ids, rmask, lmask, out);
}